// round 2
// baseline (speedup 1.0000x reference)
#include <cuda_runtime.h>
#include <math.h>

#define N 8192
#define D 256
#define NLAB 8
#define BM 128
#define BN 128
#define BK 16

// ---- device global scratch (no allocations allowed) ----
__device__ float g_Fs[N * D];     // sorted, normalized features (8 MB)
__device__ int   g_pos[N];        // original row -> sorted position
__device__ int   g_lab_s[N];      // sorted labels
__device__ int   g_spk_s[N];      // sorted speaker ids
__device__ float g_num[N];
__device__ float g_den[N];
__device__ float g_total;
__device__ int   g_count;

// ------------------------------------------------------------------
__global__ void zero_kernel() {
    int i = blockIdx.x * blockDim.x + threadIdx.x;
    if (i < N) { g_num[i] = 0.f; g_den[i] = 0.f; }
    if (i == 0) { g_total = 0.f; g_count = 0; }
}

// ------------------------------------------------------------------
// Single-block deterministic counting sort by label (8 buckets).
// Also auto-detects whether labels/speaker_ids arrived as int32 or int64:
// if int64 (little-endian, values < 2^31), every odd 32-bit word within the
// first 8192 words is a zero high-half. For int32 data those words are real
// labels -- probability all 4096 are zero is (1/8)^4096 ~ 0.
__global__ void sort_kernel(const int* __restrict__ lab32,
                            const int* __restrict__ spk32) {
    __shared__ int sh_cnt[256][NLAB];
    __shared__ int sh_tot[NLAB];
    __shared__ int sh_bucket[NLAB];
    __shared__ int sh_flag;
    const int t = threadIdx.x;

    if (t == 0) sh_flag = 0;
    __syncthreads();

    int anynz = 0;
    #pragma unroll
    for (int j = 0; j < 16; j++) {
        int idx = 2 * (t * 16 + j) + 1;   // odd words 1..8191
        anynz |= lab32[idx];
    }
    if (anynz) atomicOr(&sh_flag, 1);
    __syncthreads();
    const int is64 = (sh_flag == 0);

    const int base = t * 32;
    int cnt[NLAB];
    #pragma unroll
    for (int l = 0; l < NLAB; l++) cnt[l] = 0;
    for (int j = 0; j < 32; j++) {
        int i = base + j;
        int l = is64 ? lab32[2 * i] : lab32[i];
        cnt[l]++;
    }
    #pragma unroll
    for (int l = 0; l < NLAB; l++) sh_cnt[t][l] = cnt[l];
    __syncthreads();

    // exclusive scan over the 256 chunks, one label per thread
    if (t < NLAB) {
        int run = 0;
        for (int c = 0; c < 256; c++) {
            int v = sh_cnt[c][t];
            sh_cnt[c][t] = run;
            run += v;
        }
        sh_tot[t] = run;
    }
    __syncthreads();
    if (t == 0) {
        int run = 0;
        for (int l = 0; l < NLAB; l++) { sh_bucket[l] = run; run += sh_tot[l]; }
    }
    __syncthreads();

    int run[NLAB];
    #pragma unroll
    for (int l = 0; l < NLAB; l++) run[l] = sh_bucket[l] + sh_cnt[t][l];
    for (int j = 0; j < 32; j++) {
        int i = base + j;
        int l = is64 ? lab32[2 * i] : lab32[i];
        int s = is64 ? spk32[2 * i] : spk32[i];
        int p = run[l]++;
        g_pos[i]   = p;
        g_lab_s[p] = l;
        g_spk_s[p] = s;
    }
}

// ------------------------------------------------------------------
// One block (64 threads) per row: L2-normalize and scatter to sorted pos.
__global__ void gather_norm_kernel(const float* __restrict__ feat) {
    const int row = blockIdx.x;
    const int t = threadIdx.x;  // 64 threads, D/4 = 64 float4s
    float4 v = reinterpret_cast<const float4*>(feat + (size_t)row * D)[t];
    float ss = v.x * v.x + v.y * v.y + v.z * v.z + v.w * v.w;
    #pragma unroll
    for (int o = 16; o; o >>= 1) ss += __shfl_xor_sync(0xffffffffu, ss, o);
    __shared__ float sw[2];
    if ((t & 31) == 0) sw[t >> 5] = ss;
    __syncthreads();
    float inv = 1.f / fmaxf(sqrtf(sw[0] + sw[1]), 1e-12f);
    int p = g_pos[row];
    float4 o4 = make_float4(v.x * inv, v.y * inv, v.z * inv, v.w * inv);
    reinterpret_cast<float4*>(g_Fs + (size_t)p * D)[t] = o4;
}

// ------------------------------------------------------------------
// Banded tiled SGEMM (sim = F F^T, sorted domain) fused with the NTXent
// epilogue. Tiles whose row/col label ranges don't intersect are skipped.
__global__ void __launch_bounds__(256) gemm_epilogue_kernel() {
    const int rs = blockIdx.y * BM;
    const int cs = blockIdx.x * BN;

    // band skip: labels sorted ascending
    if (g_lab_s[cs] > g_lab_s[rs + BM - 1] ||
        g_lab_s[cs + BN - 1] < g_lab_s[rs]) return;

    __shared__ float As[BK][BM];
    __shared__ float Bs[BK][BN];
    __shared__ int labn[BN];
    __shared__ int spkn[BN];

    const int t  = threadIdx.x;
    const int tx = t & 15;
    const int ty = t >> 4;

    if (t < BN) { labn[t] = g_lab_s[cs + t]; spkn[t] = g_spk_s[cs + t]; }

    float acc[8][8];
    #pragma unroll
    for (int i = 0; i < 8; i++)
        #pragma unroll
        for (int j = 0; j < 8; j++) acc[i][j] = 0.f;

    for (int kt = 0; kt < D; kt += BK) {
        #pragma unroll
        for (int q0 = 0; q0 < 2; q0++) {
            int q   = t + q0 * 256;        // 0..511
            int row = q >> 2;              // 0..127
            int kq  = (q & 3) * 4;         // 0,4,8,12
            float4 a = *reinterpret_cast<const float4*>(
                g_Fs + (size_t)(rs + row) * D + kt + kq);
            As[kq][row] = a.x; As[kq + 1][row] = a.y;
            As[kq + 2][row] = a.z; As[kq + 3][row] = a.w;
            float4 b = *reinterpret_cast<const float4*>(
                g_Fs + (size_t)(cs + row) * D + kt + kq);
            Bs[kq][row] = b.x; Bs[kq + 1][row] = b.y;
            Bs[kq + 2][row] = b.z; Bs[kq + 3][row] = b.w;
        }
        __syncthreads();
        #pragma unroll
        for (int k = 0; k < BK; k++) {
            float a[8], b[8];
            *reinterpret_cast<float4*>(a)     = *reinterpret_cast<float4*>(&As[k][ty * 8]);
            *reinterpret_cast<float4*>(a + 4) = *reinterpret_cast<float4*>(&As[k][ty * 8 + 4]);
            *reinterpret_cast<float4*>(b)     = *reinterpret_cast<float4*>(&Bs[k][tx * 8]);
            *reinterpret_cast<float4*>(b + 4) = *reinterpret_cast<float4*>(&Bs[k][tx * 8 + 4]);
            #pragma unroll
            for (int i = 0; i < 8; i++)
                #pragma unroll
                for (int j = 0; j < 8; j++)
                    acc[i][j] = fmaf(a[i], b[j], acc[i][j]);
        }
        __syncthreads();
    }

    // epilogue: exp + masked accumulation
    const float invT = 1.25f;  // 1 / 0.8
    #pragma unroll
    for (int i = 0; i < 8; i++) {
        int gi = rs + ty * 8 + i;
        int li = g_lab_s[gi];
        int si = g_spk_s[gi];
        float num = 0.f, den = 0.f;
        #pragma unroll
        for (int j = 0; j < 8; j++) {
            int cj = tx * 8 + j;
            int gj = cs + cj;
            if (labn[cj] == li && gi != gj) {
                float e = __expf(acc[i][j] * invT);
                den += e;
                if (spkn[cj] == si) num += e;
            }
        }
        if (den != 0.f) atomicAdd(&g_den[gi], den);
        if (num != 0.f) atomicAdd(&g_num[gi], num);
    }
}

// ------------------------------------------------------------------
__global__ void finalize_kernel() {
    int i = blockIdx.x * blockDim.x + threadIdx.x;
    float loss = 0.f;
    int c = 0;
    if (i < N) {
        float num = g_num[i];
        float den = g_den[i] + 1e-7f;
        if (num > 0.f) { loss = -(logf(num) - logf(den)); c = 1; }
    }
    #pragma unroll
    for (int o = 16; o; o >>= 1) {
        loss += __shfl_xor_sync(0xffffffffu, loss, o);
        c    += __shfl_xor_sync(0xffffffffu, c, o);
    }
    __shared__ float sl[8];
    __shared__ int   sc[8];
    int lane = threadIdx.x & 31, w = threadIdx.x >> 5;
    if (lane == 0) { sl[w] = loss; sc[w] = c; }
    __syncthreads();
    if (threadIdx.x == 0) {
        float tl = 0.f; int tc = 0;
        for (int q = 0; q < 8; q++) { tl += sl[q]; tc += sc[q]; }
        atomicAdd(&g_total, tl);
        atomicAdd(&g_count, tc);
    }
}

__global__ void write_out_kernel(float* out) {
    out[0] = (g_count > 0) ? g_total / (float)g_count : 0.f;
}

// ------------------------------------------------------------------
extern "C" void kernel_launch(void* const* d_in, const int* in_sizes, int n_in,
                              void* d_out, int out_size) {
    const float* feat = (const float*)d_in[0];
    const int*   lab  = (const int*)d_in[1];
    const int*   spk  = (const int*)d_in[2];
    float* out = (float*)d_out;

    zero_kernel<<<32, 256>>>();
    sort_kernel<<<1, 256>>>(lab, spk);
    gather_norm_kernel<<<N, 64>>>(feat);
    dim3 grid(N / BN, N / BM);
    gemm_epilogue_kernel<<<grid, 256>>>();
    finalize_kernel<<<32, 256>>>();
    write_out_kernel<<<1, 1>>>(out);
}

// round 3
// speedup vs baseline: 1.1308x; 1.1308x over previous
#include <cuda_runtime.h>
#include <math.h>

#define N 8192
#define D 256
#define NLAB 8
#define BM 128
#define BN 128
#define BK 16
#define BMP (BM + 4)   // smem row pad: cuts STS write conflicts

// ---- device global scratch (no allocations allowed) ----
__device__ float g_Fs[N * D];     // sorted, normalized features (8 MB)
__device__ int   g_pos[N];        // original row -> sorted position
__device__ int   g_lab_s[N];      // sorted labels
__device__ int   g_spk_s[N];      // sorted speaker ids
__device__ float g_num[N];
__device__ float g_den[N];
__device__ float g_total;
__device__ int   g_count;

// ---- packed f32x2 helpers (Blackwell double-rate fp32) ----
__device__ __forceinline__ unsigned long long dup2(float x) {
    unsigned long long r;
    asm("mov.b64 %0, {%1, %1};" : "=l"(r) : "r"(__float_as_uint(x)));
    return r;
}
__device__ __forceinline__ void ffma2(unsigned long long& d,
                                      unsigned long long a,
                                      unsigned long long b) {
    asm("fma.rn.f32x2 %0, %1, %2, %0;" : "+l"(d) : "l"(a), "l"(b));
}

// ------------------------------------------------------------------
__global__ void zero_kernel() {
    int i = blockIdx.x * blockDim.x + threadIdx.x;
    if (i < N) { g_num[i] = 0.f; g_den[i] = 0.f; }
    if (i == 0) { g_total = 0.f; g_count = 0; }
}

// ------------------------------------------------------------------
// Single-block deterministic counting sort by label (8 buckets).
// Auto-detects int32 vs int64 input encoding (see R1 notes).
__global__ void sort_kernel(const int* __restrict__ lab32,
                            const int* __restrict__ spk32) {
    __shared__ int sh_cnt[256][NLAB];
    __shared__ int sh_tot[NLAB];
    __shared__ int sh_bucket[NLAB];
    __shared__ int sh_flag;
    const int t = threadIdx.x;

    if (t == 0) sh_flag = 0;
    __syncthreads();

    int anynz = 0;
    #pragma unroll
    for (int j = 0; j < 16; j++) {
        int idx = 2 * (t * 16 + j) + 1;
        anynz |= lab32[idx];
    }
    if (anynz) atomicOr(&sh_flag, 1);
    __syncthreads();
    const int is64 = (sh_flag == 0);

    const int base = t * 32;
    int cnt[NLAB];
    #pragma unroll
    for (int l = 0; l < NLAB; l++) cnt[l] = 0;
    for (int j = 0; j < 32; j++) {
        int i = base + j;
        int l = is64 ? lab32[2 * i] : lab32[i];
        cnt[l]++;
    }
    #pragma unroll
    for (int l = 0; l < NLAB; l++) sh_cnt[t][l] = cnt[l];
    __syncthreads();

    if (t < NLAB) {
        int run = 0;
        for (int c = 0; c < 256; c++) {
            int v = sh_cnt[c][t];
            sh_cnt[c][t] = run;
            run += v;
        }
        sh_tot[t] = run;
    }
    __syncthreads();
    if (t == 0) {
        int run = 0;
        for (int l = 0; l < NLAB; l++) { sh_bucket[l] = run; run += sh_tot[l]; }
    }
    __syncthreads();

    int run[NLAB];
    #pragma unroll
    for (int l = 0; l < NLAB; l++) run[l] = sh_bucket[l] + sh_cnt[t][l];
    for (int j = 0; j < 32; j++) {
        int i = base + j;
        int l = is64 ? lab32[2 * i] : lab32[i];
        int s = is64 ? spk32[2 * i] : spk32[i];
        int p = run[l]++;
        g_pos[i]   = p;
        g_lab_s[p] = l;
        g_spk_s[p] = s;
    }
}

// ------------------------------------------------------------------
__global__ void gather_norm_kernel(const float* __restrict__ feat) {
    const int row = blockIdx.x;
    const int t = threadIdx.x;  // 64 threads, D/4 = 64 float4s
    float4 v = reinterpret_cast<const float4*>(feat + (size_t)row * D)[t];
    float ss = v.x * v.x + v.y * v.y + v.z * v.z + v.w * v.w;
    #pragma unroll
    for (int o = 16; o; o >>= 1) ss += __shfl_xor_sync(0xffffffffu, ss, o);
    __shared__ float sw[2];
    if ((t & 31) == 0) sw[t >> 5] = ss;
    __syncthreads();
    float inv = 1.f / fmaxf(sqrtf(sw[0] + sw[1]), 1e-12f);
    int p = g_pos[row];
    float4 o4 = make_float4(v.x * inv, v.y * inv, v.z * inv, v.w * inv);
    reinterpret_cast<float4*>(g_Fs + (size_t)p * D)[t] = o4;
}

// ------------------------------------------------------------------
// Banded tiled SGEMM (sim = F F^T, sorted domain) with packed f32x2 FMA
// and register-staged global prefetch. Fused NTXent epilogue.
__global__ void __launch_bounds__(256, 2) gemm_epilogue_kernel() {
    const int rs = blockIdx.y * BM;
    const int cs = blockIdx.x * BN;

    if (g_lab_s[cs] > g_lab_s[rs + BM - 1] ||
        g_lab_s[cs + BN - 1] < g_lab_s[rs]) return;

    __shared__ __align__(16) float As[BK][BMP];
    __shared__ __align__(16) float Bs[BK][BMP];
    __shared__ int labn[BN];
    __shared__ int spkn[BN];

    const int t  = threadIdx.x;
    const int tx = t & 15;
    const int ty = t >> 4;

    if (t < BN) { labn[t] = g_lab_s[cs + t]; spkn[t] = g_spk_s[cs + t]; }

    // staging layout: thread loads rows (row0, row0+64) at k-cols [kq, kq+4)
    const int row0 = t >> 2;
    const int kq   = (t & 3) * 4;

    const float* __restrict__ pArow0 = g_Fs + (size_t)(rs + row0) * D + kq;
    const float* __restrict__ pArow1 = g_Fs + (size_t)(rs + row0 + 64) * D + kq;
    const float* __restrict__ pBrow0 = g_Fs + (size_t)(cs + row0) * D + kq;
    const float* __restrict__ pBrow1 = g_Fs + (size_t)(cs + row0 + 64) * D + kq;

    float4 pa0 = *reinterpret_cast<const float4*>(pArow0);
    float4 pa1 = *reinterpret_cast<const float4*>(pArow1);
    float4 pb0 = *reinterpret_cast<const float4*>(pBrow0);
    float4 pb1 = *reinterpret_cast<const float4*>(pBrow1);

    unsigned long long acc[8][4];
    #pragma unroll
    for (int i = 0; i < 8; i++)
        #pragma unroll
        for (int p = 0; p < 4; p++) acc[i][p] = 0ull;

    for (int kt = 0; kt < D; kt += BK) {
        // commit staged registers to smem
        As[kq + 0][row0] = pa0.x; As[kq + 1][row0] = pa0.y;
        As[kq + 2][row0] = pa0.z; As[kq + 3][row0] = pa0.w;
        As[kq + 0][row0 + 64] = pa1.x; As[kq + 1][row0 + 64] = pa1.y;
        As[kq + 2][row0 + 64] = pa1.z; As[kq + 3][row0 + 64] = pa1.w;
        Bs[kq + 0][row0] = pb0.x; Bs[kq + 1][row0] = pb0.y;
        Bs[kq + 2][row0] = pb0.z; Bs[kq + 3][row0] = pb0.w;
        Bs[kq + 0][row0 + 64] = pb1.x; Bs[kq + 1][row0 + 64] = pb1.y;
        Bs[kq + 2][row0 + 64] = pb1.z; Bs[kq + 3][row0 + 64] = pb1.w;
        __syncthreads();

        // prefetch next K-slice (LDG latency hidden under the FFMA2 block)
        if (kt + BK < D) {
            int o = kt + BK;
            pa0 = *reinterpret_cast<const float4*>(pArow0 + o);
            pa1 = *reinterpret_cast<const float4*>(pArow1 + o);
            pb0 = *reinterpret_cast<const float4*>(pBrow0 + o);
            pb1 = *reinterpret_cast<const float4*>(pBrow1 + o);
        }

        #pragma unroll
        for (int k = 0; k < BK; k++) {
            const float4 a0 = *reinterpret_cast<const float4*>(&As[k][ty * 8]);
            const float4 a1 = *reinterpret_cast<const float4*>(&As[k][ty * 8 + 4]);
            const ulonglong2 b0 = *reinterpret_cast<const ulonglong2*>(&Bs[k][tx * 8]);
            const ulonglong2 b1 = *reinterpret_cast<const ulonglong2*>(&Bs[k][tx * 8 + 4]);
            unsigned long long av[8];
            av[0] = dup2(a0.x); av[1] = dup2(a0.y);
            av[2] = dup2(a0.z); av[3] = dup2(a0.w);
            av[4] = dup2(a1.x); av[5] = dup2(a1.y);
            av[6] = dup2(a1.z); av[7] = dup2(a1.w);
            unsigned long long bv[4] = { b0.x, b0.y, b1.x, b1.y };
            #pragma unroll
            for (int i = 0; i < 8; i++)
                #pragma unroll
                for (int p = 0; p < 4; p++)
                    ffma2(acc[i][p], av[i], bv[p]);
        }
        __syncthreads();
    }

    // epilogue: exp + masked accumulation
    const float invT = 1.25f;  // 1 / 0.8
    #pragma unroll
    for (int i = 0; i < 8; i++) {
        int gi = rs + ty * 8 + i;
        int li = g_lab_s[gi];
        int si = g_spk_s[gi];
        float num = 0.f, den = 0.f;
        #pragma unroll
        for (int p = 0; p < 4; p++) {
            unsigned long long v = acc[i][p];
            float v0 = __uint_as_float((unsigned int)(v & 0xffffffffull));
            float v1 = __uint_as_float((unsigned int)(v >> 32));
            int cj0 = tx * 8 + 2 * p;
            int gj0 = cs + cj0;
            if (labn[cj0] == li && gi != gj0) {
                float e = __expf(v0 * invT);
                den += e;
                if (spkn[cj0] == si) num += e;
            }
            int cj1 = cj0 + 1;
            int gj1 = cs + cj1;
            if (labn[cj1] == li && gi != gj1) {
                float e = __expf(v1 * invT);
                den += e;
                if (spkn[cj1] == si) num += e;
            }
        }
        if (den != 0.f) atomicAdd(&g_den[gi], den);
        if (num != 0.f) atomicAdd(&g_num[gi], num);
    }
}

// ------------------------------------------------------------------
__global__ void finalize_kernel() {
    int i = blockIdx.x * blockDim.x + threadIdx.x;
    float loss = 0.f;
    int c = 0;
    if (i < N) {
        float num = g_num[i];
        float den = g_den[i] + 1e-7f;
        if (num > 0.f) { loss = -(logf(num) - logf(den)); c = 1; }
    }
    #pragma unroll
    for (int o = 16; o; o >>= 1) {
        loss += __shfl_xor_sync(0xffffffffu, loss, o);
        c    += __shfl_xor_sync(0xffffffffu, c, o);
    }
    __shared__ float sl[8];
    __shared__ int   sc[8];
    int lane = threadIdx.x & 31, w = threadIdx.x >> 5;
    if (lane == 0) { sl[w] = loss; sc[w] = c; }
    __syncthreads();
    if (threadIdx.x == 0) {
        float tl = 0.f; int tc = 0;
        for (int q = 0; q < 8; q++) { tl += sl[q]; tc += sc[q]; }
        atomicAdd(&g_total, tl);
        atomicAdd(&g_count, tc);
    }
}

__global__ void write_out_kernel(float* out) {
    out[0] = (g_count > 0) ? g_total / (float)g_count : 0.f;
}

// ------------------------------------------------------------------
extern "C" void kernel_launch(void* const* d_in, const int* in_sizes, int n_in,
                              void* d_out, int out_size) {
    const float* feat = (const float*)d_in[0];
    const int*   lab  = (const int*)d_in[1];
    const int*   spk  = (const int*)d_in[2];
    float* out = (float*)d_out;

    zero_kernel<<<32, 256>>>();
    sort_kernel<<<1, 256>>>(lab, spk);
    gather_norm_kernel<<<N, 64>>>(feat);
    dim3 grid(N / BN, N / BM);
    gemm_epilogue_kernel<<<grid, 256>>>();
    finalize_kernel<<<32, 256>>>();
    write_out_kernel<<<1, 1>>>(out);
}

// round 5
// speedup vs baseline: 1.6847x; 1.4898x over previous
#include <cuda_runtime.h>
#include <cuda_bf16.h>
#include <math.h>
#include <stdint.h>

#define N 8192
#define D 256
#define NLAB 8
#define BM 128
#define BN 128
#define KC 768            // concatenated K: [hi|lo|hi] x [hi|hi|lo]
#define CHUNK 64          // bf16 per chunk row = 128 bytes
#define NCHUNK (KC / CHUNK)   // 12

// ---- device global scratch (no allocations allowed) ----
__device__ __nv_bfloat16 g_A[N * KC];   // sorted rows, [hi|lo|hi]
__device__ __nv_bfloat16 g_B[N * KC];   // sorted rows, [hi|hi|lo]
__device__ int   g_pos[N];
__device__ int   g_lab_s[N];
__device__ int   g_spk_s[N];
__device__ float g_num[N];
__device__ float g_den[N];
__device__ float g_total;
__device__ int   g_count;

// ---- dynamic smem layout (relative to 1024-aligned base) ----
#define SM_A0 0
#define SM_A1 16384
#define SM_B0 32768
#define SM_B1 49152
#define SM_LABC 65536
#define SM_SPKC 66048
#define SM_LABR 66560
#define SM_SPKR 67072
#define SM_END  67584
#define SMEM_DYN (SM_END + 1024)

// ------------------------------------------------------------------ PTX helpers
__device__ __forceinline__ uint32_t smem_u32(const void* p) {
    uint32_t a;
    asm("{ .reg .u64 t; cvta.to.shared.u64 t, %1; cvt.u32.u64 %0, t; }"
        : "=r"(a) : "l"(p));
    return a;
}
__device__ __forceinline__ void cp16(uint32_t dst, const void* src) {
    asm volatile("cp.async.cg.shared.global [%0], [%1], 16;"
                 :: "r"(dst), "l"(src) : "memory");
}
__device__ __forceinline__ void cp_commit() {
    asm volatile("cp.async.commit_group;" ::: "memory");
}
template <int NN>
__device__ __forceinline__ void cp_wait() {
    asm volatile("cp.async.wait_group %0;" :: "n"(NN) : "memory");
}
__device__ __forceinline__ void ldm_x4(uint32_t* r, uint32_t addr) {
    asm volatile("ldmatrix.sync.aligned.m8n8.x4.shared.b16 {%0,%1,%2,%3}, [%4];"
        : "=r"(r[0]), "=r"(r[1]), "=r"(r[2]), "=r"(r[3]) : "r"(addr));
}
__device__ __forceinline__ void mma_bf16(float* c, const uint32_t* a,
                                         uint32_t b0, uint32_t b1) {
    asm volatile(
        "mma.sync.aligned.m16n8k16.row.col.f32.bf16.bf16.f32 "
        "{%0,%1,%2,%3}, {%4,%5,%6,%7}, {%8,%9}, {%0,%1,%2,%3};"
        : "+f"(c[0]), "+f"(c[1]), "+f"(c[2]), "+f"(c[3])
        : "r"(a[0]), "r"(a[1]), "r"(a[2]), "r"(a[3]), "r"(b0), "r"(b1));
}

// ------------------------------------------------------------------
// Single-block deterministic counting sort by label (8 buckets), with
// int32/int64 input auto-detection. Also zeroes the accumulators.
__global__ void sort_kernel(const int* __restrict__ lab32,
                            const int* __restrict__ spk32) {
    __shared__ int sh_cnt[256][NLAB];
    __shared__ int sh_tot[NLAB];
    __shared__ int sh_bucket[NLAB];
    __shared__ int sh_flag;
    const int t = threadIdx.x;

    // fold in the zero-init (saves one launch)
    #pragma unroll
    for (int j = 0; j < 32; j++) {
        int i = t * 32 + j;
        g_num[i] = 0.f; g_den[i] = 0.f;
    }
    if (t == 0) { g_total = 0.f; g_count = 0; sh_flag = 0; }
    __syncthreads();

    int anynz = 0;
    #pragma unroll
    for (int j = 0; j < 16; j++) {
        int idx = 2 * (t * 16 + j) + 1;
        anynz |= lab32[idx];
    }
    if (anynz) atomicOr(&sh_flag, 1);
    __syncthreads();
    const int is64 = (sh_flag == 0);

    const int base = t * 32;
    int cnt[NLAB];
    #pragma unroll
    for (int l = 0; l < NLAB; l++) cnt[l] = 0;
    for (int j = 0; j < 32; j++) {
        int i = base + j;
        int l = is64 ? lab32[2 * i] : lab32[i];
        cnt[l]++;
    }
    #pragma unroll
    for (int l = 0; l < NLAB; l++) sh_cnt[t][l] = cnt[l];
    __syncthreads();

    if (t < NLAB) {
        int run = 0;
        for (int c = 0; c < 256; c++) {
            int v = sh_cnt[c][t];
            sh_cnt[c][t] = run;
            run += v;
        }
        sh_tot[t] = run;
    }
    __syncthreads();
    if (t == 0) {
        int run = 0;
        for (int l = 0; l < NLAB; l++) { sh_bucket[l] = run; run += sh_tot[l]; }
    }
    __syncthreads();

    int run[NLAB];
    #pragma unroll
    for (int l = 0; l < NLAB; l++) run[l] = sh_bucket[l] + sh_cnt[t][l];
    for (int j = 0; j < 32; j++) {
        int i = base + j;
        int l = is64 ? lab32[2 * i] : lab32[i];
        int s = is64 ? spk32[2 * i] : spk32[i];
        int p = run[l]++;
        g_pos[i]   = p;
        g_lab_s[p] = l;
        g_spk_s[p] = s;
    }
}

// ------------------------------------------------------------------
// L2-normalize, split into bf16 hi/lo, scatter to sorted position.
// g_A row = [hi | lo | hi], g_B row = [hi | hi | lo].
__global__ void gather_norm_kernel(const float* __restrict__ feat) {
    const int row = blockIdx.x;
    const int t = threadIdx.x;  // 64 threads, D/4 = 64 float4s
    float4 v = reinterpret_cast<const float4*>(feat + (size_t)row * D)[t];
    float ss = v.x * v.x + v.y * v.y + v.z * v.z + v.w * v.w;
    #pragma unroll
    for (int o = 16; o; o >>= 1) ss += __shfl_xor_sync(0xffffffffu, ss, o);
    __shared__ float sw[2];
    if ((t & 31) == 0) sw[t >> 5] = ss;
    __syncthreads();
    float inv = 1.f / fmaxf(sqrtf(sw[0] + sw[1]), 1e-12f);
    int p = g_pos[row];
    float c[4] = { v.x * inv, v.y * inv, v.z * inv, v.w * inv };
    __nv_bfloat16* A = g_A + (size_t)p * KC;
    __nv_bfloat16* B = g_B + (size_t)p * KC;
    #pragma unroll
    for (int j = 0; j < 4; j++) {
        int col = 4 * t + j;
        __nv_bfloat16 hi = __float2bfloat16(c[j]);
        __nv_bfloat16 lo = __float2bfloat16(c[j] - __bfloat162float(hi));
        A[col] = hi; A[256 + col] = lo; A[512 + col] = hi;
        B[col] = hi; B[256 + col] = hi; B[512 + col] = lo;
    }
}

// ------------------------------------------------------------------
// chunk loader: 128 rows x 64 bf16 (128B), XOR-swizzled, via cp.async
__device__ __forceinline__ void issue_chunk(uint32_t sa, uint32_t sbb,
                                            const __nv_bfloat16* gA,
                                            const __nv_bfloat16* gB, int t) {
    #pragma unroll
    for (int q = 0; q < 4; q++) {
        int u = t + q * 256;           // 0..1023
        int row = u >> 3;
        int jj  = u & 7;
        uint32_t bo = row * 128 + jj * 16;
        uint32_t sw = bo ^ ((bo >> 3) & 0x70);
        cp16(sa + sw,  gA + (size_t)row * KC + jj * 8);
        cp16(sbb + sw, gB + (size_t)row * KC + jj * 8);
    }
    cp_commit();
}

// ------------------------------------------------------------------
// Banded bf16-split mma.sync GEMM (sim = F F^T) + fused NTXent epilogue.
__global__ void __launch_bounds__(256, 2) mma_epilogue_kernel() {
    const int rs = blockIdx.y * BM;
    const int cs = blockIdx.x * BN;
    if (g_lab_s[cs] > g_lab_s[rs + BM - 1] ||
        g_lab_s[cs + BN - 1] < g_lab_s[rs]) return;

    extern __shared__ char smem_raw[];
    uint32_t sb_raw = smem_u32(smem_raw);
    uint32_t pad = ((sb_raw + 1023u) & ~1023u) - sb_raw;
    char* smem = smem_raw + pad;
    uint32_t sb = sb_raw + pad;

    const int t    = threadIdx.x;
    const int lane = t & 31;
    const int wid  = t >> 5;
    const int wm   = wid >> 2;   // 0..1 : 64-row slab
    const int wn   = wid & 3;    // 0..3 : 32-col slab

    if (t < 128) {
        ((int*)(smem + SM_LABC))[t] = g_lab_s[cs + t];
        ((int*)(smem + SM_SPKC))[t] = g_spk_s[cs + t];
        ((int*)(smem + SM_LABR))[t] = g_lab_s[rs + t];
        ((int*)(smem + SM_SPKR))[t] = g_spk_s[rs + t];
    }
    __syncthreads();

    const __nv_bfloat16* gA = g_A + (size_t)rs * KC;
    const __nv_bfloat16* gB = g_B + (size_t)cs * KC;

    // prologue: chunks 0 and 1 in flight
    issue_chunk(sb + SM_A0, sb + SM_B0, gA, gB, t);
    issue_chunk(sb + SM_A1, sb + SM_B1, gA + CHUNK, gB + CHUNK, t);

    float acc[4][2][2][4];
    #pragma unroll
    for (int mi = 0; mi < 4; mi++)
        #pragma unroll
        for (int nj = 0; nj < 2; nj++)
            #pragma unroll
            for (int ns = 0; ns < 2; ns++)
                #pragma unroll
                for (int r = 0; r < 4; r++) acc[mi][nj][ns][r] = 0.f;

    const int mrow8 = ((lane >> 3) & 1) * 8 + (lane & 7);  // ldmatrix row-in-16
    const int khalf = (lane >> 4) * 16;                    // ldmatrix k-byte half

    for (int c = 0; c < NCHUNK; c++) {
        if (c < NCHUNK - 1) cp_wait<1>(); else cp_wait<0>();
        __syncthreads();

        const uint32_t abase = sb + (c & 1 ? SM_A1 : SM_A0);
        const uint32_t bbase = sb + (c & 1 ? SM_B1 : SM_B0);

        #pragma unroll
        for (int ks = 0; ks < 4; ks++) {
            uint32_t afr[4][4];
            #pragma unroll
            for (int mi = 0; mi < 4; mi++) {
                int row = wm * 64 + mi * 16 + mrow8;
                uint32_t kb = ks * 32 + khalf;
                ldm_x4(afr[mi], abase + row * 128 + (kb ^ ((row & 7) << 4)));
            }
            uint32_t bfr[2][4];
            #pragma unroll
            for (int nj = 0; nj < 2; nj++) {
                int row = wn * 32 + nj * 16 + mrow8;
                uint32_t kb = ks * 32 + khalf;
                ldm_x4(bfr[nj], bbase + row * 128 + (kb ^ ((row & 7) << 4)));
            }
            #pragma unroll
            for (int mi = 0; mi < 4; mi++)
                #pragma unroll
                for (int nj = 0; nj < 2; nj++) {
                    mma_bf16(acc[mi][nj][0], afr[mi], bfr[nj][0], bfr[nj][2]);
                    mma_bf16(acc[mi][nj][1], afr[mi], bfr[nj][1], bfr[nj][3]);
                }
        }
        __syncthreads();
        if (c + 2 < NCHUNK)
            issue_chunk(sb + (c & 1 ? SM_A1 : SM_A0), sb + (c & 1 ? SM_B1 : SM_B0),
                        gA + (c + 2) * CHUNK, gB + (c + 2) * CHUNK, t);
    }

    // ---- epilogue: masked exp + row reduction ----
    const int* labc = (const int*)(smem + SM_LABC);
    const int* spkc = (const int*)(smem + SM_SPKC);
    const int* labr = (const int*)(smem + SM_LABR);
    const int* spkr = (const int*)(smem + SM_SPKR);
    const float invT = 1.25f;  // 1/0.8

    // this thread's 8 column attributes
    int clab[2][2][2], cspk[2][2][2], ccol[2][2][2];
    #pragma unroll
    for (int nj = 0; nj < 2; nj++)
        #pragma unroll
        for (int ns = 0; ns < 2; ns++)
            #pragma unroll
            for (int j = 0; j < 2; j++) {
                int col = wn * 32 + nj * 16 + ns * 8 + (lane & 3) * 2 + j;
                ccol[nj][ns][j] = col;
                clab[nj][ns][j] = labc[col];
                cspk[nj][ns][j] = spkc[col];
            }

    #pragma unroll
    for (int mi = 0; mi < 4; mi++) {
        #pragma unroll
        for (int half = 0; half < 2; half++) {
            int row = wm * 64 + mi * 16 + (lane >> 2) + half * 8;
            int gi = rs + row;
            int li = labr[row];
            int si = spkr[row];
            float num = 0.f, den = 0.f;
            #pragma unroll
            for (int nj = 0; nj < 2; nj++)
                #pragma unroll
                for (int ns = 0; ns < 2; ns++)
                    #pragma unroll
                    for (int j = 0; j < 2; j++) {
                        if (clab[nj][ns][j] == li && gi != cs + ccol[nj][ns][j]) {
                            float e = __expf(acc[mi][nj][ns][j + 2 * half] * invT);
                            den += e;
                            if (cspk[nj][ns][j] == si) num += e;
                        }
                    }
            num += __shfl_xor_sync(0xffffffffu, num, 1);
            num += __shfl_xor_sync(0xffffffffu, num, 2);
            den += __shfl_xor_sync(0xffffffffu, den, 1);
            den += __shfl_xor_sync(0xffffffffu, den, 2);
            if ((lane & 3) == 0) {
                if (num != 0.f) atomicAdd(&g_num[gi], num);
                if (den != 0.f) atomicAdd(&g_den[gi], den);
            }
        }
    }
}

// ------------------------------------------------------------------
__global__ void finalize_kernel() {
    int i = blockIdx.x * blockDim.x + threadIdx.x;
    float loss = 0.f;
    int c = 0;
    if (i < N) {
        float num = g_num[i];
        float den = g_den[i] + 1e-7f;
        if (num > 0.f) { loss = -(logf(num) - logf(den)); c = 1; }
    }
    #pragma unroll
    for (int o = 16; o; o >>= 1) {
        loss += __shfl_xor_sync(0xffffffffu, loss, o);
        c    += __shfl_xor_sync(0xffffffffu, c, o);
    }
    __shared__ float sl[8];
    __shared__ int   sc[8];
    int lane = threadIdx.x & 31, w = threadIdx.x >> 5;
    if (lane == 0) { sl[w] = loss; sc[w] = c; }
    __syncthreads();
    if (threadIdx.x == 0) {
        float tl = 0.f; int tc = 0;
        for (int q = 0; q < 8; q++) { tl += sl[q]; tc += sc[q]; }
        atomicAdd(&g_total, tl);
        atomicAdd(&g_count, tc);
    }
}

__global__ void write_out_kernel(float* out) {
    out[0] = (g_count > 0) ? g_total / (float)g_count : 0.f;
}

// ------------------------------------------------------------------
extern "C" void kernel_launch(void* const* d_in, const int* in_sizes, int n_in,
                              void* d_out, int out_size) {
    const float* feat = (const float*)d_in[0];
    const int*   lab  = (const int*)d_in[1];
    const int*   spk  = (const int*)d_in[2];
    float* out = (float*)d_out;

    cudaFuncSetAttribute(mma_epilogue_kernel,
                         cudaFuncAttributeMaxDynamicSharedMemorySize, SMEM_DYN);

    sort_kernel<<<1, 256>>>(lab, spk);
    gather_norm_kernel<<<N, 64>>>(feat);
    dim3 grid(N / BN, N / BM);
    mma_epilogue_kernel<<<grid, 256, SMEM_DYN>>>();
    finalize_kernel<<<32, 256>>>();
    write_out_kernel<<<1, 1>>>(out);
}

// round 6
// speedup vs baseline: 1.9631x; 1.1653x over previous
#include <cuda_runtime.h>
#include <cuda_bf16.h>
#include <math.h>
#include <stdint.h>

#define N 8192
#define D 256
#define NLAB 8
#define BM 128
#define BN 128
#define KC 768            // concatenated K: [hi|lo|hi] x [hi|hi|lo]
#define CHUNK 64          // bf16 per chunk row = 128 bytes
#define NCHUNK (KC / CHUNK)   // 12
#define NTB (N / BM)          // 64 tile rows
#define NTRI (NTB * (NTB + 1) / 2)   // 2080 lower-triangular tiles

// ---- device global scratch (no allocations allowed) ----
__device__ __nv_bfloat16 g_A[N * KC];   // sorted rows, [hi|lo|hi]
__device__ __nv_bfloat16 g_B[N * KC];   // sorted rows, [hi|hi|lo]
__device__ int   g_pos[N];
__device__ int   g_lab_s[N];
__device__ int   g_spk_s[N];
__device__ float g_num[N];
__device__ float g_den[N];
__device__ float g_total;
__device__ int   g_count;

// ---- dynamic smem layout (relative to 1024-aligned base) ----
#define SM_A0 0
#define SM_A1 16384
#define SM_B0 32768
#define SM_B1 49152
#define SM_LABC 65536
#define SM_SPKC 66048
#define SM_LABR 66560
#define SM_SPKR 67072
#define SM_END  67584
#define SMEM_DYN (SM_END + 1024)

// ------------------------------------------------------------------ PTX helpers
__device__ __forceinline__ uint32_t smem_u32(const void* p) {
    uint32_t a;
    asm("{ .reg .u64 t; cvta.to.shared.u64 t, %1; cvt.u32.u64 %0, t; }"
        : "=r"(a) : "l"(p));
    return a;
}
__device__ __forceinline__ void cp16(uint32_t dst, const void* src) {
    asm volatile("cp.async.cg.shared.global [%0], [%1], 16;"
                 :: "r"(dst), "l"(src) : "memory");
}
__device__ __forceinline__ void cp_commit() {
    asm volatile("cp.async.commit_group;" ::: "memory");
}
template <int NN>
__device__ __forceinline__ void cp_wait() {
    asm volatile("cp.async.wait_group %0;" :: "n"(NN) : "memory");
}
__device__ __forceinline__ void ldm_x4(uint32_t* r, uint32_t addr) {
    asm volatile("ldmatrix.sync.aligned.m8n8.x4.shared.b16 {%0,%1,%2,%3}, [%4];"
        : "=r"(r[0]), "=r"(r[1]), "=r"(r[2]), "=r"(r[3]) : "r"(addr));
}
__device__ __forceinline__ void mma_bf16(float* c, const uint32_t* a,
                                         uint32_t b0, uint32_t b1) {
    asm volatile(
        "mma.sync.aligned.m16n8k16.row.col.f32.bf16.bf16.f32 "
        "{%0,%1,%2,%3}, {%4,%5,%6,%7}, {%8,%9}, {%0,%1,%2,%3};"
        : "+f"(c[0]), "+f"(c[1]), "+f"(c[2]), "+f"(c[3])
        : "r"(a[0]), "r"(a[1]), "r"(a[2]), "r"(a[3]), "r"(b0), "r"(b1));
}

// ------------------------------------------------------------------
// Single-block deterministic counting sort by label (8 buckets), with
// int32/int64 input auto-detection. Also zeroes the accumulators.
__global__ void sort_kernel(const int* __restrict__ lab32,
                            const int* __restrict__ spk32) {
    __shared__ int sh_cnt[256][NLAB];
    __shared__ int sh_tot[NLAB];
    __shared__ int sh_bucket[NLAB];
    __shared__ int sh_flag;
    const int t = threadIdx.x;

    #pragma unroll
    for (int j = 0; j < 32; j++) {
        int i = t * 32 + j;
        g_num[i] = 0.f; g_den[i] = 0.f;
    }
    if (t == 0) { g_total = 0.f; g_count = 0; sh_flag = 0; }
    __syncthreads();

    int anynz = 0;
    #pragma unroll
    for (int j = 0; j < 16; j++) {
        int idx = 2 * (t * 16 + j) + 1;
        anynz |= lab32[idx];
    }
    if (anynz) atomicOr(&sh_flag, 1);
    __syncthreads();
    const int is64 = (sh_flag == 0);

    const int base = t * 32;
    int cnt[NLAB];
    #pragma unroll
    for (int l = 0; l < NLAB; l++) cnt[l] = 0;
    for (int j = 0; j < 32; j++) {
        int i = base + j;
        int l = is64 ? lab32[2 * i] : lab32[i];
        cnt[l]++;
    }
    #pragma unroll
    for (int l = 0; l < NLAB; l++) sh_cnt[t][l] = cnt[l];
    __syncthreads();

    if (t < NLAB) {
        int run = 0;
        for (int c = 0; c < 256; c++) {
            int v = sh_cnt[c][t];
            sh_cnt[c][t] = run;
            run += v;
        }
        sh_tot[t] = run;
    }
    __syncthreads();
    if (t == 0) {
        int run = 0;
        for (int l = 0; l < NLAB; l++) { sh_bucket[l] = run; run += sh_tot[l]; }
    }
    __syncthreads();

    int run[NLAB];
    #pragma unroll
    for (int l = 0; l < NLAB; l++) run[l] = sh_bucket[l] + sh_cnt[t][l];
    for (int j = 0; j < 32; j++) {
        int i = base + j;
        int l = is64 ? lab32[2 * i] : lab32[i];
        int s = is64 ? spk32[2 * i] : spk32[i];
        int p = run[l]++;
        g_pos[i]   = p;
        g_lab_s[p] = l;
        g_spk_s[p] = s;
    }
}

// ------------------------------------------------------------------
// L2-normalize, split into bf16 hi/lo, scatter to sorted position.
// g_A row = [hi | lo | hi], g_B row = [hi | hi | lo].
__global__ void gather_norm_kernel(const float* __restrict__ feat) {
    const int row = blockIdx.x;
    const int t = threadIdx.x;  // 64 threads, D/4 = 64 float4s
    float4 v = reinterpret_cast<const float4*>(feat + (size_t)row * D)[t];
    float ss = v.x * v.x + v.y * v.y + v.z * v.z + v.w * v.w;
    #pragma unroll
    for (int o = 16; o; o >>= 1) ss += __shfl_xor_sync(0xffffffffu, ss, o);
    __shared__ float sw[2];
    if ((t & 31) == 0) sw[t >> 5] = ss;
    __syncthreads();
    float inv = 1.f / fmaxf(sqrtf(sw[0] + sw[1]), 1e-12f);
    int p = g_pos[row];
    float c[4] = { v.x * inv, v.y * inv, v.z * inv, v.w * inv };
    __nv_bfloat16* A = g_A + (size_t)p * KC;
    __nv_bfloat16* B = g_B + (size_t)p * KC;
    #pragma unroll
    for (int j = 0; j < 4; j++) {
        int col = 4 * t + j;
        __nv_bfloat16 hi = __float2bfloat16(c[j]);
        __nv_bfloat16 lo = __float2bfloat16(c[j] - __bfloat162float(hi));
        A[col] = hi; A[256 + col] = lo; A[512 + col] = hi;
        B[col] = hi; B[256 + col] = hi; B[512 + col] = lo;
    }
}

// ------------------------------------------------------------------
__device__ __forceinline__ void issue_chunk(uint32_t sa, uint32_t sbb,
                                            const __nv_bfloat16* gA,
                                            const __nv_bfloat16* gB, int t) {
    #pragma unroll
    for (int q = 0; q < 4; q++) {
        int u = t + q * 256;           // 0..1023
        int row = u >> 3;
        int jj  = u & 7;
        uint32_t bo = row * 128 + jj * 16;
        uint32_t sw = bo ^ ((bo >> 3) & 0x70);
        cp16(sa + sw,  gA + (size_t)row * KC + jj * 8);
        cp16(sbb + sw, gB + (size_t)row * KC + jj * 8);
    }
    cp_commit();
}

// ------------------------------------------------------------------
// Lower-triangular banded bf16-split mma.sync GEMM + symmetric epilogue.
__global__ void __launch_bounds__(256, 2) mma_epilogue_kernel() {
    // decode lower-triangular tile index: bi >= bj
    const int idx = blockIdx.x;
    int bi = (int)((sqrtf(8.0f * (float)idx + 1.0f) - 1.0f) * 0.5f);
    while ((bi + 1) * (bi + 2) / 2 <= idx) bi++;
    while (bi * (bi + 1) / 2 > idx) bi--;
    const int bj = idx - bi * (bi + 1) / 2;
    const int rs = bi * BM;
    const int cs = bj * BN;
    const bool diag = (bi == bj);

    if (g_lab_s[cs] > g_lab_s[rs + BM - 1] ||
        g_lab_s[cs + BN - 1] < g_lab_s[rs]) return;

    extern __shared__ char smem_raw[];
    uint32_t sb_raw = smem_u32(smem_raw);
    uint32_t pad = ((sb_raw + 1023u) & ~1023u) - sb_raw;
    char* smem = smem_raw + pad;
    uint32_t sb = sb_raw + pad;

    const int t    = threadIdx.x;
    const int lane = t & 31;
    const int wid  = t >> 5;
    const int wm   = wid >> 2;   // 0..1 : 64-row slab
    const int wn   = wid & 3;    // 0..3 : 32-col slab

    if (t < 128) {
        ((int*)(smem + SM_LABC))[t] = g_lab_s[cs + t];
        ((int*)(smem + SM_SPKC))[t] = g_spk_s[cs + t];
        ((int*)(smem + SM_LABR))[t] = g_lab_s[rs + t];
        ((int*)(smem + SM_SPKR))[t] = g_spk_s[rs + t];
    }
    __syncthreads();

    const __nv_bfloat16* gA = g_A + (size_t)rs * KC;
    const __nv_bfloat16* gB = g_B + (size_t)cs * KC;

    issue_chunk(sb + SM_A0, sb + SM_B0, gA, gB, t);
    issue_chunk(sb + SM_A1, sb + SM_B1, gA + CHUNK, gB + CHUNK, t);

    float acc[4][2][2][4];
    #pragma unroll
    for (int mi = 0; mi < 4; mi++)
        #pragma unroll
        for (int nj = 0; nj < 2; nj++)
            #pragma unroll
            for (int ns = 0; ns < 2; ns++)
                #pragma unroll
                for (int r = 0; r < 4; r++) acc[mi][nj][ns][r] = 0.f;

    const int mrow8 = ((lane >> 3) & 1) * 8 + (lane & 7);
    const int khalf = (lane >> 4) * 16;

    for (int c = 0; c < NCHUNK; c++) {
        if (c < NCHUNK - 1) cp_wait<1>(); else cp_wait<0>();
        __syncthreads();

        const uint32_t abase = sb + (c & 1 ? SM_A1 : SM_A0);
        const uint32_t bbase = sb + (c & 1 ? SM_B1 : SM_B0);

        #pragma unroll
        for (int ks = 0; ks < 4; ks++) {
            uint32_t afr[4][4];
            #pragma unroll
            for (int mi = 0; mi < 4; mi++) {
                int row = wm * 64 + mi * 16 + mrow8;
                uint32_t kb = ks * 32 + khalf;
                ldm_x4(afr[mi], abase + row * 128 + (kb ^ ((row & 7) << 4)));
            }
            uint32_t bfr[2][4];
            #pragma unroll
            for (int nj = 0; nj < 2; nj++) {
                int row = wn * 32 + nj * 16 + mrow8;
                uint32_t kb = ks * 32 + khalf;
                ldm_x4(bfr[nj], bbase + row * 128 + (kb ^ ((row & 7) << 4)));
            }
            #pragma unroll
            for (int mi = 0; mi < 4; mi++)
                #pragma unroll
                for (int nj = 0; nj < 2; nj++) {
                    mma_bf16(acc[mi][nj][0], afr[mi], bfr[nj][0], bfr[nj][2]);
                    mma_bf16(acc[mi][nj][1], afr[mi], bfr[nj][1], bfr[nj][3]);
                }
        }
        __syncthreads();
        if (c + 2 < NCHUNK)
            issue_chunk(sb + (c & 1 ? SM_A1 : SM_A0), sb + (c & 1 ? SM_B1 : SM_B0),
                        gA + (c + 2) * CHUNK, gB + (c + 2) * CHUNK, t);
    }

    // ---- epilogue: masked exp + row AND (off-diag) column reduction ----
    const int* labc = (const int*)(smem + SM_LABC);
    const int* spkc = (const int*)(smem + SM_SPKC);
    const int* labr = (const int*)(smem + SM_LABR);
    const int* spkr = (const int*)(smem + SM_SPKR);
    const float invT = 1.25f;  // 1/0.8

    int clab[2][2][2], cspk[2][2][2], ccol[2][2][2];
    float colnum[2][2][2], colden[2][2][2];
    #pragma unroll
    for (int nj = 0; nj < 2; nj++)
        #pragma unroll
        for (int ns = 0; ns < 2; ns++)
            #pragma unroll
            for (int j = 0; j < 2; j++) {
                int col = wn * 32 + nj * 16 + ns * 8 + (lane & 3) * 2 + j;
                ccol[nj][ns][j] = col;
                clab[nj][ns][j] = labc[col];
                cspk[nj][ns][j] = spkc[col];
                colnum[nj][ns][j] = 0.f;
                colden[nj][ns][j] = 0.f;
            }

    #pragma unroll
    for (int mi = 0; mi < 4; mi++) {
        #pragma unroll
        for (int half = 0; half < 2; half++) {
            int row = wm * 64 + mi * 16 + (lane >> 2) + half * 8;
            int gi = rs + row;
            int li = labr[row];
            int si = spkr[row];
            float num = 0.f, den = 0.f;
            #pragma unroll
            for (int nj = 0; nj < 2; nj++)
                #pragma unroll
                for (int ns = 0; ns < 2; ns++)
                    #pragma unroll
                    for (int j = 0; j < 2; j++) {
                        if (clab[nj][ns][j] == li && gi != cs + ccol[nj][ns][j]) {
                            float e = __expf(acc[mi][nj][ns][j + 2 * half] * invT);
                            den += e;
                            colden[nj][ns][j] += e;
                            if (cspk[nj][ns][j] == si) {
                                num += e;
                                colnum[nj][ns][j] += e;
                            }
                        }
                    }
            num += __shfl_xor_sync(0xffffffffu, num, 1);
            num += __shfl_xor_sync(0xffffffffu, num, 2);
            den += __shfl_xor_sync(0xffffffffu, den, 1);
            den += __shfl_xor_sync(0xffffffffu, den, 2);
            if ((lane & 3) == 0) {
                if (num != 0.f) atomicAdd(&g_num[gi], num);
                if (den != 0.f) atomicAdd(&g_den[gi], den);
            }
        }
    }

    // column contribution = transposed-tile rows (symmetry), off-diag only
    if (!diag) {
        #pragma unroll
        for (int nj = 0; nj < 2; nj++)
            #pragma unroll
            for (int ns = 0; ns < 2; ns++)
                #pragma unroll
                for (int j = 0; j < 2; j++) {
                    float cn = colnum[nj][ns][j];
                    float cd = colden[nj][ns][j];
                    cn += __shfl_xor_sync(0xffffffffu, cn, 4);
                    cn += __shfl_xor_sync(0xffffffffu, cn, 8);
                    cn += __shfl_xor_sync(0xffffffffu, cn, 16);
                    cd += __shfl_xor_sync(0xffffffffu, cd, 4);
                    cd += __shfl_xor_sync(0xffffffffu, cd, 8);
                    cd += __shfl_xor_sync(0xffffffffu, cd, 16);
                    if (lane < 4) {
                        int gj = cs + ccol[nj][ns][j];
                        if (cn != 0.f) atomicAdd(&g_num[gj], cn);
                        if (cd != 0.f) atomicAdd(&g_den[gj], cd);
                    }
                }
    }
}

// ------------------------------------------------------------------
__global__ void finalize_kernel() {
    int i = blockIdx.x * blockDim.x + threadIdx.x;
    float loss = 0.f;
    int c = 0;
    if (i < N) {
        float num = g_num[i];
        float den = g_den[i] + 1e-7f;
        if (num > 0.f) { loss = -(logf(num) - logf(den)); c = 1; }
    }
    #pragma unroll
    for (int o = 16; o; o >>= 1) {
        loss += __shfl_xor_sync(0xffffffffu, loss, o);
        c    += __shfl_xor_sync(0xffffffffu, c, o);
    }
    __shared__ float sl[8];
    __shared__ int   sc[8];
    int lane = threadIdx.x & 31, w = threadIdx.x >> 5;
    if (lane == 0) { sl[w] = loss; sc[w] = c; }
    __syncthreads();
    if (threadIdx.x == 0) {
        float tl = 0.f; int tc = 0;
        for (int q = 0; q < 8; q++) { tl += sl[q]; tc += sc[q]; }
        atomicAdd(&g_total, tl);
        atomicAdd(&g_count, tc);
    }
}

__global__ void write_out_kernel(float* out) {
    out[0] = (g_count > 0) ? g_total / (float)g_count : 0.f;
}

// ------------------------------------------------------------------
extern "C" void kernel_launch(void* const* d_in, const int* in_sizes, int n_in,
                              void* d_out, int out_size) {
    const float* feat = (const float*)d_in[0];
    const int*   lab  = (const int*)d_in[1];
    const int*   spk  = (const int*)d_in[2];
    float* out = (float*)d_out;

    cudaFuncSetAttribute(mma_epilogue_kernel,
                         cudaFuncAttributeMaxDynamicSharedMemorySize, SMEM_DYN);

    sort_kernel<<<1, 256>>>(lab, spk);
    gather_norm_kernel<<<N, 64>>>(feat);
    mma_epilogue_kernel<<<NTRI, 256, SMEM_DYN>>>();
    finalize_kernel<<<32, 256>>>();
    write_out_kernel<<<1, 1>>>(out);
}

// round 7
// speedup vs baseline: 2.4360x; 1.2409x over previous
#include <cuda_runtime.h>
#include <cuda_bf16.h>
#include <math.h>
#include <stdint.h>

#define N 8192
#define D 256
#define NLAB 8
#define BM 128
#define BN 128
#define KA 512            // A row: [hi(256) | lo(256)]
#define CHUNK 64          // bf16 per chunk row = 128 bytes
#define NCHUNK 8          // A chunks (B uses first 4 = hi)
#define NTB (N / BM)      // 64 tile rows
#define NTRI (NTB * (NTB + 1) / 2)   // 2080 lower-triangular tiles

// ---- device global scratch (no allocations allowed) ----
__device__ __nv_bfloat16 g_F[N * KA];   // sorted rows, [hi|lo]
__device__ int   g_pos[N];
__device__ int   g_lab_s[N];
__device__ int   g_spk_s[N];
__device__ float g_num[N];
__device__ float g_den[N];

// ---- dynamic smem layout (relative to 1024-aligned base) ----
#define SM_A0   0
#define SM_A1   16384
#define SM_B0   32768          // B0..B3 resident: + k*16384
#define SM_LABC 98304
#define SM_SPKC 98816
#define SM_LABR 99328
#define SM_SPKR 99840
#define SM_END  100352
#define SMEM_DYN (SM_END + 1024)

// ------------------------------------------------------------------ PTX helpers
__device__ __forceinline__ uint32_t smem_u32(const void* p) {
    uint32_t a;
    asm("{ .reg .u64 t; cvta.to.shared.u64 t, %1; cvt.u32.u64 %0, t; }"
        : "=r"(a) : "l"(p));
    return a;
}
__device__ __forceinline__ void cp16(uint32_t dst, const void* src) {
    asm volatile("cp.async.cg.shared.global [%0], [%1], 16;"
                 :: "r"(dst), "l"(src) : "memory");
}
__device__ __forceinline__ void cp_commit() {
    asm volatile("cp.async.commit_group;" ::: "memory");
}
template <int NN>
__device__ __forceinline__ void cp_wait() {
    asm volatile("cp.async.wait_group %0;" :: "n"(NN) : "memory");
}
__device__ __forceinline__ void ldm_x4(uint32_t* r, uint32_t addr) {
    asm volatile("ldmatrix.sync.aligned.m8n8.x4.shared.b16 {%0,%1,%2,%3}, [%4];"
        : "=r"(r[0]), "=r"(r[1]), "=r"(r[2]), "=r"(r[3]) : "r"(addr));
}
__device__ __forceinline__ void mma_bf16(float* c, const uint32_t* a,
                                         uint32_t b0, uint32_t b1) {
    asm volatile(
        "mma.sync.aligned.m16n8k16.row.col.f32.bf16.bf16.f32 "
        "{%0,%1,%2,%3}, {%4,%5,%6,%7}, {%8,%9}, {%0,%1,%2,%3};"
        : "+f"(c[0]), "+f"(c[1]), "+f"(c[2]), "+f"(c[3])
        : "r"(a[0]), "r"(a[1]), "r"(a[2]), "r"(a[3]), "r"(b0), "r"(b1));
}

// ------------------------------------------------------------------
// Single-block deterministic counting sort by label (8 buckets), with
// int32/int64 input auto-detection. Also zeroes the accumulators.
__global__ void sort_kernel(const int* __restrict__ lab32,
                            const int* __restrict__ spk32) {
    __shared__ int sh_cnt[256][NLAB];
    __shared__ int sh_tot[NLAB];
    __shared__ int sh_bucket[NLAB];
    __shared__ int sh_flag;
    const int t = threadIdx.x;

    #pragma unroll
    for (int j = 0; j < 32; j++) {
        int i = t * 32 + j;
        g_num[i] = 0.f; g_den[i] = 0.f;
    }
    if (t == 0) sh_flag = 0;
    __syncthreads();

    int anynz = 0;
    #pragma unroll
    for (int j = 0; j < 16; j++) {
        int idx = 2 * (t * 16 + j) + 1;
        anynz |= lab32[idx];
    }
    if (anynz) atomicOr(&sh_flag, 1);
    __syncthreads();
    const int is64 = (sh_flag == 0);

    const int base = t * 32;
    int cnt[NLAB];
    #pragma unroll
    for (int l = 0; l < NLAB; l++) cnt[l] = 0;
    for (int j = 0; j < 32; j++) {
        int i = base + j;
        int l = is64 ? lab32[2 * i] : lab32[i];
        cnt[l]++;
    }
    #pragma unroll
    for (int l = 0; l < NLAB; l++) sh_cnt[t][l] = cnt[l];
    __syncthreads();

    if (t < NLAB) {
        int run = 0;
        for (int c = 0; c < 256; c++) {
            int v = sh_cnt[c][t];
            sh_cnt[c][t] = run;
            run += v;
        }
        sh_tot[t] = run;
    }
    __syncthreads();
    if (t == 0) {
        int run = 0;
        for (int l = 0; l < NLAB; l++) { sh_bucket[l] = run; run += sh_tot[l]; }
    }
    __syncthreads();

    int run[NLAB];
    #pragma unroll
    for (int l = 0; l < NLAB; l++) run[l] = sh_bucket[l] + sh_cnt[t][l];
    for (int j = 0; j < 32; j++) {
        int i = base + j;
        int l = is64 ? lab32[2 * i] : lab32[i];
        int s = is64 ? spk32[2 * i] : spk32[i];
        int p = run[l]++;
        g_pos[i]   = p;
        g_lab_s[p] = l;
        g_spk_s[p] = s;
    }
}

// ------------------------------------------------------------------
// L2-normalize, split into bf16 hi/lo, scatter to sorted position.
// g_F row = [hi | lo].
__global__ void gather_norm_kernel(const float* __restrict__ feat) {
    const int row = blockIdx.x;
    const int t = threadIdx.x;  // 64 threads, D/4 = 64 float4s
    float4 v = reinterpret_cast<const float4*>(feat + (size_t)row * D)[t];
    float ss = v.x * v.x + v.y * v.y + v.z * v.z + v.w * v.w;
    #pragma unroll
    for (int o = 16; o; o >>= 1) ss += __shfl_xor_sync(0xffffffffu, ss, o);
    __shared__ float sw[2];
    if ((t & 31) == 0) sw[t >> 5] = ss;
    __syncthreads();
    float inv = 1.f / fmaxf(sqrtf(sw[0] + sw[1]), 1e-12f);
    int p = g_pos[row];
    float c[4] = { v.x * inv, v.y * inv, v.z * inv, v.w * inv };
    __nv_bfloat16* F = g_F + (size_t)p * KA;
    __nv_bfloat16 hi4[4], lo4[4];
    #pragma unroll
    for (int j = 0; j < 4; j++) {
        hi4[j] = __float2bfloat16(c[j]);
        lo4[j] = __float2bfloat16(c[j] - __bfloat162float(hi4[j]));
    }
    *reinterpret_cast<uint2*>(F + 4 * t)       = *reinterpret_cast<uint2*>(hi4);
    *reinterpret_cast<uint2*>(F + 256 + 4 * t) = *reinterpret_cast<uint2*>(lo4);
}

// ------------------------------------------------------------------
// load one 128x64 bf16 chunk (128B rows), XOR-swizzled, via cp.async
__device__ __forceinline__ void issue_one(uint32_t dst,
                                          const __nv_bfloat16* g, int t) {
    #pragma unroll
    for (int q = 0; q < 4; q++) {
        int u = t + q * 256;           // 0..1023
        int row = u >> 3;
        int jj  = u & 7;
        uint32_t bo = row * 128 + jj * 16;
        uint32_t sw = bo ^ ((bo >> 3) & 0x70);
        cp16(dst + sw, g + (size_t)row * KA + jj * 8);
    }
}

// ------------------------------------------------------------------
// Lower-triangular banded bf16-split mma.sync GEMM + symmetric epilogue.
// A streams [hi|lo] through 2 buffers; B (= hi half) stays resident in 4.
__global__ void __launch_bounds__(256, 2) mma_epilogue_kernel() {
    const int idx = blockIdx.x;
    int bi = (int)((sqrtf(8.0f * (float)idx + 1.0f) - 1.0f) * 0.5f);
    while ((bi + 1) * (bi + 2) / 2 <= idx) bi++;
    while (bi * (bi + 1) / 2 > idx) bi--;
    const int bj = idx - bi * (bi + 1) / 2;
    const int rs = bi * BM;
    const int cs = bj * BN;
    const bool diag = (bi == bj);

    if (g_lab_s[cs] > g_lab_s[rs + BM - 1] ||
        g_lab_s[cs + BN - 1] < g_lab_s[rs]) return;

    extern __shared__ char smem_raw[];
    uint32_t sb_raw = smem_u32(smem_raw);
    uint32_t pad = ((sb_raw + 1023u) & ~1023u) - sb_raw;
    char* smem = smem_raw + pad;
    uint32_t sb = sb_raw + pad;

    const int t    = threadIdx.x;
    const int lane = t & 31;
    const int wid  = t >> 5;
    const int wm   = wid >> 2;   // 0..1 : 64-row slab
    const int wn   = wid & 3;    // 0..3 : 32-col slab

    if (t < 128) {
        ((int*)(smem + SM_LABC))[t] = g_lab_s[cs + t];
        ((int*)(smem + SM_SPKC))[t] = g_spk_s[cs + t];
        ((int*)(smem + SM_LABR))[t] = g_lab_s[rs + t];
        ((int*)(smem + SM_SPKR))[t] = g_spk_s[rs + t];
    }
    __syncthreads();

    const __nv_bfloat16* gA = g_F + (size_t)rs * KA;
    const __nv_bfloat16* gB = g_F + (size_t)cs * KA;   // hi half

    // prologue: G0={A0,B0} G1={A1,B1} G2={B2} G3={B3}
    issue_one(sb + SM_A0, gA, t);
    issue_one(sb + SM_B0, gB, t);
    cp_commit();
    issue_one(sb + SM_A1, gA + CHUNK, t);
    issue_one(sb + SM_B0 + 16384, gB + CHUNK, t);
    cp_commit();
    issue_one(sb + SM_B0 + 32768, gB + 2 * CHUNK, t);
    cp_commit();
    issue_one(sb + SM_B0 + 49152, gB + 3 * CHUNK, t);
    cp_commit();

    float acc[4][2][2][4];
    #pragma unroll
    for (int mi = 0; mi < 4; mi++)
        #pragma unroll
        for (int nj = 0; nj < 2; nj++)
            #pragma unroll
            for (int ns = 0; ns < 2; ns++)
                #pragma unroll
                for (int r = 0; r < 4; r++) acc[mi][nj][ns][r] = 0.f;

    const int mrow8 = ((lane >> 3) & 1) * 8 + (lane & 7);
    const int khalf = (lane >> 4) * 16;

    for (int c = 0; c < NCHUNK; c++) {
        if (c < 2) cp_wait<3>();
        else if (c < 7) cp_wait<1>();
        else cp_wait<0>();
        __syncthreads();

        const uint32_t abase = sb + (c & 1 ? SM_A1 : SM_A0);
        const uint32_t bbase = sb + SM_B0 + (c & 3) * 16384;

        #pragma unroll
        for (int ks = 0; ks < 4; ks++) {
            uint32_t afr[4][4];
            #pragma unroll
            for (int mi = 0; mi < 4; mi++) {
                int row = wm * 64 + mi * 16 + mrow8;
                uint32_t kb = ks * 32 + khalf;
                ldm_x4(afr[mi], abase + row * 128 + (kb ^ ((row & 7) << 4)));
            }
            uint32_t bfr[2][4];
            #pragma unroll
            for (int nj = 0; nj < 2; nj++) {
                int row = wn * 32 + nj * 16 + mrow8;
                uint32_t kb = ks * 32 + khalf;
                ldm_x4(bfr[nj], bbase + row * 128 + (kb ^ ((row & 7) << 4)));
            }
            #pragma unroll
            for (int mi = 0; mi < 4; mi++)
                #pragma unroll
                for (int nj = 0; nj < 2; nj++) {
                    mma_bf16(acc[mi][nj][0], afr[mi], bfr[nj][0], bfr[nj][2]);
                    mma_bf16(acc[mi][nj][1], afr[mi], bfr[nj][1], bfr[nj][3]);
                }
        }
        __syncthreads();
        if (c + 2 < NCHUNK) {
            issue_one(sb + (c & 1 ? SM_A1 : SM_A0), gA + (c + 2) * CHUNK, t);
            cp_commit();
        }
    }

    // ---- epilogue: masked exp + row AND (off-diag) column reduction ----
    const int* labc = (const int*)(smem + SM_LABC);
    const int* spkc = (const int*)(smem + SM_SPKC);
    const int* labr = (const int*)(smem + SM_LABR);
    const int* spkr = (const int*)(smem + SM_SPKR);
    const float invT = 1.25f;  // 1/0.8

    int clab[2][2][2], cspk[2][2][2], ccol[2][2][2];
    float colnum[2][2][2], colden[2][2][2];
    #pragma unroll
    for (int nj = 0; nj < 2; nj++)
        #pragma unroll
        for (int ns = 0; ns < 2; ns++)
            #pragma unroll
            for (int j = 0; j < 2; j++) {
                int col = wn * 32 + nj * 16 + ns * 8 + (lane & 3) * 2 + j;
                ccol[nj][ns][j] = col;
                clab[nj][ns][j] = labc[col];
                cspk[nj][ns][j] = spkc[col];
                colnum[nj][ns][j] = 0.f;
                colden[nj][ns][j] = 0.f;
            }

    #pragma unroll
    for (int mi = 0; mi < 4; mi++) {
        #pragma unroll
        for (int half = 0; half < 2; half++) {
            int row = wm * 64 + mi * 16 + (lane >> 2) + half * 8;
            int gi = rs + row;
            int li = labr[row];
            int si = spkr[row];
            float num = 0.f, den = 0.f;
            #pragma unroll
            for (int nj = 0; nj < 2; nj++)
                #pragma unroll
                for (int ns = 0; ns < 2; ns++)
                    #pragma unroll
                    for (int j = 0; j < 2; j++) {
                        if (clab[nj][ns][j] == li && gi != cs + ccol[nj][ns][j]) {
                            float e = __expf(acc[mi][nj][ns][j + 2 * half] * invT);
                            den += e;
                            colden[nj][ns][j] += e;
                            if (cspk[nj][ns][j] == si) {
                                num += e;
                                colnum[nj][ns][j] += e;
                            }
                        }
                    }
            num += __shfl_xor_sync(0xffffffffu, num, 1);
            num += __shfl_xor_sync(0xffffffffu, num, 2);
            den += __shfl_xor_sync(0xffffffffu, den, 1);
            den += __shfl_xor_sync(0xffffffffu, den, 2);
            if ((lane & 3) == 0) {
                if (num != 0.f) atomicAdd(&g_num[gi], num);
                if (den != 0.f) atomicAdd(&g_den[gi], den);
            }
        }
    }

    if (!diag) {
        #pragma unroll
        for (int nj = 0; nj < 2; nj++)
            #pragma unroll
            for (int ns = 0; ns < 2; ns++)
                #pragma unroll
                for (int j = 0; j < 2; j++) {
                    float cn = colnum[nj][ns][j];
                    float cd = colden[nj][ns][j];
                    cn += __shfl_xor_sync(0xffffffffu, cn, 4);
                    cn += __shfl_xor_sync(0xffffffffu, cn, 8);
                    cn += __shfl_xor_sync(0xffffffffu, cn, 16);
                    cd += __shfl_xor_sync(0xffffffffu, cd, 4);
                    cd += __shfl_xor_sync(0xffffffffu, cd, 8);
                    cd += __shfl_xor_sync(0xffffffffu, cd, 16);
                    if (lane < 4) {
                        int gj = cs + ccol[nj][ns][j];
                        if (cn != 0.f) atomicAdd(&g_num[gj], cn);
                        if (cd != 0.f) atomicAdd(&g_den[gj], cd);
                    }
                }
    }
}

// ------------------------------------------------------------------
// single-block fused finalize + output write
__global__ void finalize_kernel(float* out) {
    const int t = threadIdx.x;  // 1024 threads
    float loss = 0.f;
    int c = 0;
    #pragma unroll
    for (int j = 0; j < 8; j++) {
        int i = t + j * 1024;
        float num = g_num[i];
        float den = g_den[i] + 1e-7f;
        if (num > 0.f) { loss += -(logf(num) - logf(den)); c++; }
    }
    #pragma unroll
    for (int o = 16; o; o >>= 1) {
        loss += __shfl_xor_sync(0xffffffffu, loss, o);
        c    += __shfl_xor_sync(0xffffffffu, c, o);
    }
    __shared__ float sl[32];
    __shared__ int   sc[32];
    int lane = t & 31, w = t >> 5;
    if (lane == 0) { sl[w] = loss; sc[w] = c; }
    __syncthreads();
    if (t == 0) {
        float tl = 0.f; int tc = 0;
        #pragma unroll
        for (int q = 0; q < 32; q++) { tl += sl[q]; tc += sc[q]; }
        out[0] = (tc > 0) ? tl / (float)tc : 0.f;
    }
}

// ------------------------------------------------------------------
extern "C" void kernel_launch(void* const* d_in, const int* in_sizes, int n_in,
                              void* d_out, int out_size) {
    const float* feat = (const float*)d_in[0];
    const int*   lab  = (const int*)d_in[1];
    const int*   spk  = (const int*)d_in[2];
    float* out = (float*)d_out;

    cudaFuncSetAttribute(mma_epilogue_kernel,
                         cudaFuncAttributeMaxDynamicSharedMemorySize, SMEM_DYN);

    sort_kernel<<<1, 256>>>(lab, spk);
    gather_norm_kernel<<<N, 64>>>(feat);
    mma_epilogue_kernel<<<NTRI, 256, SMEM_DYN>>>();
    finalize_kernel<<<1, 1024>>>(out);
}

// round 8
// speedup vs baseline: 2.7609x; 1.1334x over previous
#include <cuda_runtime.h>
#include <cuda_bf16.h>
#include <math.h>
#include <stdint.h>

#define N 8192
#define D 256
#define NLAB 8
#define BM 128
#define BN 128
#define KA 512            // A row: [hi(256) | lo(256)]
#define CHUNK 64          // bf16 per chunk row = 128 bytes
#define NCHUNK 8          // A chunks (B uses first 4 = hi)
#define NTB (N / BM)      // 64 tile rows
#define NTRI (NTB * (NTB + 1) / 2)   // 2080 lower-triangular tiles

// ---- device global scratch (no allocations allowed) ----
__device__ __nv_bfloat16 g_F[N * KA];   // sorted rows, [hi|lo]
__device__ int   g_pos[N];
__device__ int   g_lab_s[N];
__device__ int   g_spk_s[N];
__device__ float g_num[N];
__device__ float g_den[N];

// ---- dynamic smem layout (relative to 1024-aligned base) ----
#define SM_A0   0
#define SM_A1   16384
#define SM_B0   32768          // B0..B3 resident: + k*16384
#define SM_LABC 98304
#define SM_SPKC 98816
#define SM_LABR 99328
#define SM_SPKR 99840
#define SM_END  100352
#define SMEM_DYN (SM_END + 1024)

// ------------------------------------------------------------------ PTX helpers
__device__ __forceinline__ uint32_t smem_u32(const void* p) {
    uint32_t a;
    asm("{ .reg .u64 t; cvta.to.shared.u64 t, %1; cvt.u32.u64 %0, t; }"
        : "=r"(a) : "l"(p));
    return a;
}
__device__ __forceinline__ void cp16(uint32_t dst, const void* src) {
    asm volatile("cp.async.cg.shared.global [%0], [%1], 16;"
                 :: "r"(dst), "l"(src) : "memory");
}
__device__ __forceinline__ void cp_commit() {
    asm volatile("cp.async.commit_group;" ::: "memory");
}
template <int NN>
__device__ __forceinline__ void cp_wait() {
    asm volatile("cp.async.wait_group %0;" :: "n"(NN) : "memory");
}
__device__ __forceinline__ void ldm_x4(uint32_t* r, uint32_t addr) {
    asm volatile("ldmatrix.sync.aligned.m8n8.x4.shared.b16 {%0,%1,%2,%3}, [%4];"
        : "=r"(r[0]), "=r"(r[1]), "=r"(r[2]), "=r"(r[3]) : "r"(addr));
}
__device__ __forceinline__ void mma_bf16(float* c, const uint32_t* a,
                                         uint32_t b0, uint32_t b1) {
    asm volatile(
        "mma.sync.aligned.m16n8k16.row.col.f32.bf16.bf16.f32 "
        "{%0,%1,%2,%3}, {%4,%5,%6,%7}, {%8,%9}, {%0,%1,%2,%3};"
        : "+f"(c[0]), "+f"(c[1]), "+f"(c[2]), "+f"(c[3])
        : "r"(a[0]), "r"(a[1]), "r"(a[2]), "r"(a[3]), "r"(b0), "r"(b1));
}

// ------------------------------------------------------------------
// Single-block deterministic counting sort by label (8 buckets), with
// int32/int64 input auto-detection. Also zeroes the accumulators.
__global__ void sort_kernel(const int* __restrict__ lab32,
                            const int* __restrict__ spk32) {
    __shared__ int sh_cnt[256][NLAB];
    __shared__ int sh_tot[NLAB];
    __shared__ int sh_bucket[NLAB];
    __shared__ int sh_flag;
    const int t = threadIdx.x;

    #pragma unroll
    for (int j = 0; j < 32; j++) {
        int i = t * 32 + j;
        g_num[i] = 0.f; g_den[i] = 0.f;
    }
    if (t == 0) sh_flag = 0;
    __syncthreads();

    int anynz = 0;
    #pragma unroll
    for (int j = 0; j < 16; j++) {
        int idx = 2 * (t * 16 + j) + 1;
        anynz |= lab32[idx];
    }
    if (anynz) atomicOr(&sh_flag, 1);
    __syncthreads();
    const int is64 = (sh_flag == 0);

    const int base = t * 32;
    int cnt[NLAB];
    #pragma unroll
    for (int l = 0; l < NLAB; l++) cnt[l] = 0;
    for (int j = 0; j < 32; j++) {
        int i = base + j;
        int l = is64 ? lab32[2 * i] : lab32[i];
        cnt[l]++;
    }
    #pragma unroll
    for (int l = 0; l < NLAB; l++) sh_cnt[t][l] = cnt[l];
    __syncthreads();

    if (t < NLAB) {
        int run = 0;
        for (int c = 0; c < 256; c++) {
            int v = sh_cnt[c][t];
            sh_cnt[c][t] = run;
            run += v;
        }
        sh_tot[t] = run;
    }
    __syncthreads();
    if (t == 0) {
        int run = 0;
        for (int l = 0; l < NLAB; l++) { sh_bucket[l] = run; run += sh_tot[l]; }
    }
    __syncthreads();

    int run[NLAB];
    #pragma unroll
    for (int l = 0; l < NLAB; l++) run[l] = sh_bucket[l] + sh_cnt[t][l];
    for (int j = 0; j < 32; j++) {
        int i = base + j;
        int l = is64 ? lab32[2 * i] : lab32[i];
        int s = is64 ? spk32[2 * i] : spk32[i];
        int p = run[l]++;
        g_pos[i]   = p;
        g_lab_s[p] = l;
        g_spk_s[p] = s;
    }
}

// ------------------------------------------------------------------
// L2-normalize, split into bf16 hi/lo, scatter to sorted position.
// 256-thread blocks, 4 rows per block (64 threads per row).
__global__ void gather_norm_kernel(const float* __restrict__ feat) {
    const int sub = threadIdx.x >> 6;          // 0..3: row within block
    const int row = blockIdx.x * 4 + sub;
    const int t = threadIdx.x & 63;            // 64 threads per row
    float4 v = reinterpret_cast<const float4*>(feat + (size_t)row * D)[t];
    float ss = v.x * v.x + v.y * v.y + v.z * v.z + v.w * v.w;
    #pragma unroll
    for (int o = 16; o; o >>= 1) ss += __shfl_xor_sync(0xffffffffu, ss, o);
    __shared__ float sw[8];
    const int w = threadIdx.x >> 5;            // warp id 0..7
    if ((threadIdx.x & 31) == 0) sw[w] = ss;
    __syncthreads();
    float inv = 1.f / fmaxf(sqrtf(sw[sub * 2] + sw[sub * 2 + 1]), 1e-12f);
    int p = g_pos[row];
    float c[4] = { v.x * inv, v.y * inv, v.z * inv, v.w * inv };
    __nv_bfloat16* F = g_F + (size_t)p * KA;
    __nv_bfloat16 hi4[4], lo4[4];
    #pragma unroll
    for (int j = 0; j < 4; j++) {
        hi4[j] = __float2bfloat16(c[j]);
        lo4[j] = __float2bfloat16(c[j] - __bfloat162float(hi4[j]));
    }
    *reinterpret_cast<uint2*>(F + 4 * t)       = *reinterpret_cast<uint2*>(hi4);
    *reinterpret_cast<uint2*>(F + 256 + 4 * t) = *reinterpret_cast<uint2*>(lo4);
}

// ------------------------------------------------------------------
// load one 128x64 bf16 chunk (128B rows), XOR-swizzled, via cp.async
__device__ __forceinline__ void issue_one(uint32_t dst,
                                          const __nv_bfloat16* g, int t) {
    #pragma unroll
    for (int q = 0; q < 4; q++) {
        int u = t + q * 256;           // 0..1023
        int row = u >> 3;
        int jj  = u & 7;
        uint32_t bo = row * 128 + jj * 16;
        uint32_t sw = bo ^ ((bo >> 3) & 0x70);
        cp16(dst + sw, g + (size_t)row * KA + jj * 8);
    }
}

// ------------------------------------------------------------------
// Lower-triangular banded bf16-split mma.sync GEMM + symmetric epilogue.
// Tiles enumerated by diagonal offset d = bi - bj ascending, so live
// (near-diagonal) tiles pack into the first waves; far tail exits fast.
__global__ void __launch_bounds__(256, 2) mma_epilogue_kernel() {
    const int idx = blockIdx.x;
    // cum(d) = d*(2*NTB+1-d)/2 ; find d with cum(d) <= idx < cum(d+1)
    int d = (int)(((float)(2 * NTB + 1) -
                   sqrtf((float)(2 * NTB + 1) * (2 * NTB + 1) - 8.0f * idx)) * 0.5f);
    if (d < 0) d = 0;
    if (d > NTB - 1) d = NTB - 1;
    while (d * (2 * NTB + 1 - d) / 2 > idx) d--;
    while ((d + 1) * (2 * NTB - d) / 2 <= idx) d++;
    const int bj = idx - d * (2 * NTB + 1 - d) / 2;
    const int bi = bj + d;
    const int rs = bi * BM;
    const int cs = bj * BN;
    const bool diag = (d == 0);

    if (g_lab_s[cs] > g_lab_s[rs + BM - 1] ||
        g_lab_s[cs + BN - 1] < g_lab_s[rs]) return;

    extern __shared__ char smem_raw[];
    uint32_t sb_raw = smem_u32(smem_raw);
    uint32_t pad = ((sb_raw + 1023u) & ~1023u) - sb_raw;
    char* smem = smem_raw + pad;
    uint32_t sb = sb_raw + pad;

    const int t    = threadIdx.x;
    const int lane = t & 31;
    const int wid  = t >> 5;
    const int wm   = wid >> 2;   // 0..1 : 64-row slab
    const int wn   = wid & 3;    // 0..3 : 32-col slab

    if (t < 128) {
        ((int*)(smem + SM_LABC))[t] = g_lab_s[cs + t];
        ((int*)(smem + SM_SPKC))[t] = g_spk_s[cs + t];
        ((int*)(smem + SM_LABR))[t] = g_lab_s[rs + t];
        ((int*)(smem + SM_SPKR))[t] = g_spk_s[rs + t];
    }
    __syncthreads();

    const __nv_bfloat16* gA = g_F + (size_t)rs * KA;
    const __nv_bfloat16* gB = g_F + (size_t)cs * KA;   // hi half

    issue_one(sb + SM_A0, gA, t);
    issue_one(sb + SM_B0, gB, t);
    cp_commit();
    issue_one(sb + SM_A1, gA + CHUNK, t);
    issue_one(sb + SM_B0 + 16384, gB + CHUNK, t);
    cp_commit();
    issue_one(sb + SM_B0 + 32768, gB + 2 * CHUNK, t);
    cp_commit();
    issue_one(sb + SM_B0 + 49152, gB + 3 * CHUNK, t);
    cp_commit();

    float acc[4][2][2][4];
    #pragma unroll
    for (int mi = 0; mi < 4; mi++)
        #pragma unroll
        for (int nj = 0; nj < 2; nj++)
            #pragma unroll
            for (int ns = 0; ns < 2; ns++)
                #pragma unroll
                for (int r = 0; r < 4; r++) acc[mi][nj][ns][r] = 0.f;

    const int mrow8 = ((lane >> 3) & 1) * 8 + (lane & 7);
    const int khalf = (lane >> 4) * 16;

    for (int c = 0; c < NCHUNK; c++) {
        if (c < 2) cp_wait<3>();
        else if (c < 7) cp_wait<1>();
        else cp_wait<0>();
        __syncthreads();

        const uint32_t abase = sb + (c & 1 ? SM_A1 : SM_A0);
        const uint32_t bbase = sb + SM_B0 + (c & 3) * 16384;

        #pragma unroll
        for (int ks = 0; ks < 4; ks++) {
            uint32_t afr[4][4];
            #pragma unroll
            for (int mi = 0; mi < 4; mi++) {
                int row = wm * 64 + mi * 16 + mrow8;
                uint32_t kb = ks * 32 + khalf;
                ldm_x4(afr[mi], abase + row * 128 + (kb ^ ((row & 7) << 4)));
            }
            uint32_t bfr[2][4];
            #pragma unroll
            for (int nj = 0; nj < 2; nj++) {
                int row = wn * 32 + nj * 16 + mrow8;
                uint32_t kb = ks * 32 + khalf;
                ldm_x4(bfr[nj], bbase + row * 128 + (kb ^ ((row & 7) << 4)));
            }
            #pragma unroll
            for (int mi = 0; mi < 4; mi++)
                #pragma unroll
                for (int nj = 0; nj < 2; nj++) {
                    mma_bf16(acc[mi][nj][0], afr[mi], bfr[nj][0], bfr[nj][2]);
                    mma_bf16(acc[mi][nj][1], afr[mi], bfr[nj][1], bfr[nj][3]);
                }
        }
        __syncthreads();
        if (c + 2 < NCHUNK) {
            issue_one(sb + (c & 1 ? SM_A1 : SM_A0), gA + (c + 2) * CHUNK, t);
            cp_commit();
        }
    }

    // ---- epilogue: masked exp + row AND (off-diag) column reduction ----
    const int* labc = (const int*)(smem + SM_LABC);
    const int* spkc = (const int*)(smem + SM_SPKC);
    const int* labr = (const int*)(smem + SM_LABR);
    const int* spkr = (const int*)(smem + SM_SPKR);
    const float invT = 1.25f;  // 1/0.8

    int clab[2][2][2], cspk[2][2][2], ccol[2][2][2];
    float colnum[2][2][2], colden[2][2][2];
    #pragma unroll
    for (int nj = 0; nj < 2; nj++)
        #pragma unroll
        for (int ns = 0; ns < 2; ns++)
            #pragma unroll
            for (int j = 0; j < 2; j++) {
                int col = wn * 32 + nj * 16 + ns * 8 + (lane & 3) * 2 + j;
                ccol[nj][ns][j] = col;
                clab[nj][ns][j] = labc[col];
                cspk[nj][ns][j] = spkc[col];
                colnum[nj][ns][j] = 0.f;
                colden[nj][ns][j] = 0.f;
            }

    #pragma unroll
    for (int mi = 0; mi < 4; mi++) {
        #pragma unroll
        for (int half = 0; half < 2; half++) {
            int row = wm * 64 + mi * 16 + (lane >> 2) + half * 8;
            int gi = rs + row;
            int li = labr[row];
            int si = spkr[row];
            float num = 0.f, den = 0.f;
            #pragma unroll
            for (int nj = 0; nj < 2; nj++)
                #pragma unroll
                for (int ns = 0; ns < 2; ns++)
                    #pragma unroll
                    for (int j = 0; j < 2; j++) {
                        if (clab[nj][ns][j] == li && gi != cs + ccol[nj][ns][j]) {
                            float e = __expf(acc[mi][nj][ns][j + 2 * half] * invT);
                            den += e;
                            colden[nj][ns][j] += e;
                            if (cspk[nj][ns][j] == si) {
                                num += e;
                                colnum[nj][ns][j] += e;
                            }
                        }
                    }
            num += __shfl_xor_sync(0xffffffffu, num, 1);
            num += __shfl_xor_sync(0xffffffffu, num, 2);
            den += __shfl_xor_sync(0xffffffffu, den, 1);
            den += __shfl_xor_sync(0xffffffffu, den, 2);
            if ((lane & 3) == 0) {
                if (num != 0.f) atomicAdd(&g_num[gi], num);
                if (den != 0.f) atomicAdd(&g_den[gi], den);
            }
        }
    }

    if (!diag) {
        #pragma unroll
        for (int nj = 0; nj < 2; nj++)
            #pragma unroll
            for (int ns = 0; ns < 2; ns++)
                #pragma unroll
                for (int j = 0; j < 2; j++) {
                    float cn = colnum[nj][ns][j];
                    float cd = colden[nj][ns][j];
                    cn += __shfl_xor_sync(0xffffffffu, cn, 4);
                    cn += __shfl_xor_sync(0xffffffffu, cn, 8);
                    cn += __shfl_xor_sync(0xffffffffu, cn, 16);
                    cd += __shfl_xor_sync(0xffffffffu, cd, 4);
                    cd += __shfl_xor_sync(0xffffffffu, cd, 8);
                    cd += __shfl_xor_sync(0xffffffffu, cd, 16);
                    if (lane < 4) {
                        int gj = cs + ccol[nj][ns][j];
                        if (cn != 0.f) atomicAdd(&g_num[gj], cn);
                        if (cd != 0.f) atomicAdd(&g_den[gj], cd);
                    }
                }
    }
}

// ------------------------------------------------------------------
// single-block fused finalize + output write (fast-math logs, batched loads)
__global__ void finalize_kernel(float* out) {
    const int t = threadIdx.x;  // 1024 threads
    float nums[8], dens[8];
    #pragma unroll
    for (int j = 0; j < 8; j++) {
        int i = t + j * 1024;
        nums[j] = g_num[i];
        dens[j] = g_den[i];
    }
    float loss = 0.f;
    int c = 0;
    #pragma unroll
    for (int j = 0; j < 8; j++) {
        if (nums[j] > 0.f) {
            loss += __logf(dens[j] + 1e-7f) - __logf(nums[j]);
            c++;
        }
    }
    #pragma unroll
    for (int o = 16; o; o >>= 1) {
        loss += __shfl_xor_sync(0xffffffffu, loss, o);
        c    += __shfl_xor_sync(0xffffffffu, c, o);
    }
    __shared__ float sl[32];
    __shared__ int   sc[32];
    int lane = t & 31, w = t >> 5;
    if (lane == 0) { sl[w] = loss; sc[w] = c; }
    __syncthreads();
    if (t == 0) {
        float tl = 0.f; int tc = 0;
        #pragma unroll
        for (int q = 0; q < 32; q++) { tl += sl[q]; tc += sc[q]; }
        out[0] = (tc > 0) ? tl / (float)tc : 0.f;
    }
}

// ------------------------------------------------------------------
extern "C" void kernel_launch(void* const* d_in, const int* in_sizes, int n_in,
                              void* d_out, int out_size) {
    const float* feat = (const float*)d_in[0];
    const int*   lab  = (const int*)d_in[1];
    const int*   spk  = (const int*)d_in[2];
    float* out = (float*)d_out;

    cudaFuncSetAttribute(mma_epilogue_kernel,
                         cudaFuncAttributeMaxDynamicSharedMemorySize, SMEM_DYN);

    sort_kernel<<<1, 256>>>(lab, spk);
    gather_norm_kernel<<<N / 4, 256>>>(feat);
    mma_epilogue_kernel<<<NTRI, 256, SMEM_DYN>>>();
    finalize_kernel<<<1, 1024>>>(out);
}